// round 4
// baseline (speedup 1.0000x reference)
#include <cuda_runtime.h>

#define Hh     51
#define H4     204
#define TT     1024
#define MB     8
#define NCTA   128
#define NTHR   512

// ---- shared memory layout (float offsets) ----
// sW1  : [204][52]  W_hh1 (col 51 = 0)     sW2i : [204][52] W_ih2 (col 51 = 0)
// sB1/sB2 : [204] combined biases          sWlin: [51]
// sXbuf: [2][8] double-buffered x          sH12 : [104][12] h1 rows 0..50, 51=0; h2 rows 52..102, 103=0
// sC   : [102][12] c1 rows 0..50, c2 rows 51..101
// sG1  : [4][204][12] layer-1 partials     sG2  : [6][204][12] (groups 0-3 = ih, 4-5 = hh)
#define OFF_W1    0
#define OFF_W2I   10608
#define OFF_B1    21216
#define OFF_B2    21420
#define OFF_WLIN  21624
#define OFF_XBUF  21676
#define OFF_H12   21692
#define OFF_C     22940
#define OFF_G1    24164
#define OFF_G2    33956
#define SMEM_FLOATS 48644
#define SMEM_BYTES  (SMEM_FLOATS * 4)

typedef unsigned long long u64;

__device__ __forceinline__ u64 splat2(float w) {
    unsigned int wi = __float_as_uint(w);
    u64 r;
    asm("mov.b64 %0, {%1, %1};" : "=l"(r) : "r"(wi));
    return r;
}
__device__ __forceinline__ void ffma2(u64& d, u64 a, u64 b) {
    asm("fma.rn.f32x2 %0, %1, %2, %0;" : "+l"(d) : "l"(a), "l"(b));
}
__device__ __forceinline__ float sigf(float x) {
    return __fdividef(1.0f, 1.0f + __expf(-x));
}
__device__ __forceinline__ float tanhfast(float x) {
    return 1.0f - __fdividef(2.0f, __expf(2.0f * x) + 1.0f);
}

// 8 FFMA2: accumulate w0,w1 x h[8 batch] into a0[4], a1[4]
#define DK_BODY(hr, w0s, w1s) { \
    const ulonglong2 hL = *(const ulonglong2*)(hr); \
    const ulonglong2 hH = *(const ulonglong2*)((hr) + 4); \
    const u64 p0 = splat2(w0s); \
    ffma2(a0[0], p0, hL.x); ffma2(a0[1], p0, hL.y); \
    ffma2(a0[2], p0, hH.x); ffma2(a0[3], p0, hH.y); \
    const u64 p1 = splat2(w1s); \
    ffma2(a1[0], p1, hL.x); ffma2(a1[1], p1, hL.y); \
    ffma2(a1[2], p1, hH.x); ffma2(a1[3], p1, hH.y); }

#define STORE_G(base, r, a) { ulonglong2 v; \
    v.x = (a)[0]; v.y = (a)[1]; *(ulonglong2*)((base) + (r) * 12)     = v; \
    v.x = (a)[2]; v.y = (a)[3]; *(ulonglong2*)((base) + (r) * 12 + 4) = v; }

template<int NG>
__device__ __forceinline__ float4 gsum(const float* g, int row, int bo) {
    const float* p = g + row * 12 + bo;
    float4 a = *(const float4*)p;
    #pragma unroll
    for (int k = 1; k < NG; ++k) {
        const float4 b = *(const float4*)(p + k * 2448);
        a.x += b.x; a.y += b.y; a.z += b.z; a.w += b.w;
    }
    return a;
}

template<int NG>
__device__ __forceinline__ void do_update(const float* sG, const float* sB,
                                          float* cp, float* hp, int j, int bo) {
    float4 gi = gsum<NG>(sG, j, bo);
    float4 gf = gsum<NG>(sG, 51 + j, bo);
    float4 gg = gsum<NG>(sG, 102 + j, bo);
    float4 go = gsum<NG>(sG, 153 + j, bo);
    const float bi = sB[j], bf = sB[51 + j], bg = sB[102 + j], bq = sB[153 + j];
    float4 c = *(float4*)cp, h;
    #define COMP(X) { \
        const float iv = sigf(gi.X + bi); const float fv = sigf(gf.X + bf); \
        const float gv = tanhfast(gg.X + bg); const float ov = sigf(go.X + bq); \
        const float cn = fv * c.X + iv * gv; c.X = cn; h.X = ov * tanhfast(cn); }
    COMP(x) COMP(y) COMP(z) COMP(w)
    #undef COMP
    *(float4*)cp = c;
    *(float4*)hp = h;
}

__global__ __launch_bounds__(NTHR, 1)
void lstm_seq_kernel(const float* __restrict__ input,
                     const float* __restrict__ W_ih1, const float* __restrict__ W_hh1,
                     const float* __restrict__ b_ih1, const float* __restrict__ b_hh1,
                     const float* __restrict__ W_ih2, const float* __restrict__ W_hh2,
                     const float* __restrict__ b_ih2, const float* __restrict__ b_hh2,
                     const float* __restrict__ W_lin, const float* __restrict__ b_lin,
                     float* __restrict__ out)
{
    extern __shared__ float sm[];
    float* sW1   = sm + OFF_W1;
    float* sW2i  = sm + OFF_W2I;
    float* sB1   = sm + OFF_B1;
    float* sB2   = sm + OFF_B2;
    float* sWlin = sm + OFF_WLIN;
    float* sXbuf = sm + OFF_XBUF;
    float* sH12  = sm + OFF_H12;
    float* sC    = sm + OFF_C;
    float* sG1   = sm + OFF_G1;
    float* sG2   = sm + OFF_G2;

    const int tid = threadIdx.x;
    const int b0  = blockIdx.x * MB;

    // ---------------- one-time staging ----------------
    for (int i = tid; i < H4 * Hh; i += NTHR) {
        const int r = i / Hh, k = i % Hh;
        sW1[r * 52 + k]  = W_hh1[i];
        sW2i[r * 52 + k] = W_ih2[i];
    }
    for (int r = tid; r < H4; r += NTHR) {
        sW1[r * 52 + 51]  = 0.0f;
        sW2i[r * 52 + 51] = 0.0f;
        sB1[r] = b_ih1[r] + b_hh1[r];
        sB2[r] = b_ih2[r] + b_hh2[r];
    }
    if (tid < Hh) sWlin[tid] = W_lin[tid];
    if (tid < MB) sXbuf[tid] = input[(b0 + tid) * TT];     // x(0) into buf 0
    for (int i = tid; i < 104 * 12; i += NTHR) sH12[i] = 0.0f;
    for (int i = tid; i < 102 * 12; i += NTHR) sC[i] = 0.0f;

    // ---------------- role setup ----------------
    // G1 / G2ih: tids 0..407 -> 4 k-groups x 102 row-pairs
    const int g  = (tid < 408) ? (tid / 102) : 0;
    const int j  = (tid < 408) ? (tid % 102) : 0;
    const int r0 = j, r1 = j + 102;
    const int qb = (g == 0) ? 0 : (3 * g + 1);   // quads {0-3,4-6,7-9,10-12}
    const int qc = (g == 0) ? 4 : 3;
    float wih0 = 0.0f, wih1v = 0.0f;
    if (tid < 408 && g == 0) { wih0 = W_ih1[r0]; wih1v = W_ih1[r1]; }

    // G2hh: tids 128..383, warps 4..11: 2 groups x (102 of 128) row-pairs
    int g2 = 0, jh = 0, qh = 13, qhc = 0;
    float wH0[28], wH1[28];
    #pragma unroll
    for (int i = 0; i < 28; ++i) { wH0[i] = 0.0f; wH1[i] = 0.0f; }
    const bool is_hh = (tid >= 128 && tid < 384) && (((tid - 128) & 127) < 102);
    if (tid >= 128 && tid < 384) {
        g2  = (tid - 128) >> 7;          // 0 or 1
        jh  = (tid - 128) & 127;         // 0..127, active < 102
        qh  = 13 + g2 * 7;               // quads {13-19, 20-25}
        qhc = g2 ? 6 : 7;
    }
    if (is_hh) {
        #pragma unroll
        for (int s = 0; s < 7; ++s) {
            if (s < qhc) {
                #pragma unroll
                for (int dk = 0; dk < 4; ++dk) {
                    const int col = (qh + s) * 4 + dk - 52;   // 0..51 (51 = pad)
                    if (col < 51) {
                        wH0[s * 4 + dk] = W_hh2[jh * 51 + col];
                        wH1[s * 4 + dk] = W_hh2[(jh + 102) * 51 + col];
                    }
                }
            }
        }
    }

    const float blin = b_lin[0];
    __syncthreads();

    // ---------------- pipelined time loop: TT+1 iterations, 3 barriers each ----------------
    for (int t = 0; t <= TT; ++t) {
        // ===== Phase A: gate1(t) || update2(t-1) || prefetch x(t+1) =====
        if (t < TT && tid < 408) {
            u64 a0[4] = {0,0,0,0}, a1[4] = {0,0,0,0};
            if (g == 0) {
                const float* xp = sXbuf + (t & 1) * 8;
                const ulonglong2 xL = *(const ulonglong2*)xp;
                const ulonglong2 xH = *(const ulonglong2*)(xp + 4);
                const u64 p0 = splat2(wih0), p1 = splat2(wih1v);
                ffma2(a0[0], p0, xL.x); ffma2(a0[1], p0, xL.y);
                ffma2(a0[2], p0, xH.x); ffma2(a0[3], p0, xH.y);
                ffma2(a1[0], p1, xL.x); ffma2(a1[1], p1, xL.y);
                ffma2(a1[2], p1, xH.x); ffma2(a1[3], p1, xH.y);
            }
            const float* w0p = sW1 + r0 * 52;
            const float* w1p = sW1 + r1 * 52;
            #pragma unroll
            for (int s = 0; s < 4; ++s) {
                if (s < qc) {
                    const int kk = qb + s;
                    const float4 w0 = *(const float4*)(w0p + kk * 4);
                    const float4 w1 = *(const float4*)(w1p + kk * 4);
                    const float wz0[4] = {w0.x, w0.y, w0.z, w0.w};
                    const float wz1[4] = {w1.x, w1.y, w1.z, w1.w};
                    #pragma unroll
                    for (int dk = 0; dk < 4; ++dk) {
                        const float* hr = sH12 + (kk * 4 + dk) * 12;  // h1(t-1)
                        DK_BODY(hr, wz0[dk], wz1[dk]);
                    }
                }
            }
            float* gb = sG1 + g * 2448;
            STORE_G(gb, r0, a0);
            STORE_G(gb, r1, a1);
        } else if (t > 0 && tid >= 416 && tid < 467) {
            // update2 for step t-1: 51 threads, 8 batch each
            const int ju2 = tid - 416;
            float* cp = sC + (51 + ju2) * 12;
            float* hp = sH12 + (52 + ju2) * 12;
            do_update<6>(sG2, sB2, cp,     hp,     ju2, 0);
            do_update<6>(sG2, sB2, cp + 4, hp + 4, ju2, 4);
        } else if (t + 1 < TT && (tid == 488 || tid == 489)) {
            const int pb = (tid - 488) * 4;
            float* xd = sXbuf + ((t + 1) & 1) * 8 + pb;
            #pragma unroll
            for (int q = 0; q < 4; ++q)
                xd[q] = input[(b0 + pb + q) * TT + (t + 1)];
        }
        __syncthreads();

        // ===== Phase B: update1(t) || gate2*W_hh2(t) || head(t-1) =====
        if (t < TT) {
            if (tid < 128) {
                if ((tid & 63) < 51) {
                    const int ju = tid & 63, bo1 = (tid >> 6) * 4;
                    do_update<4>(sG1, sB1, sC + ju * 12 + bo1,
                                 sH12 + ju * 12 + bo1, ju, bo1);
                }
            } else if (tid < 384) {
                if (is_hh) {
                    u64 a0[4] = {0,0,0,0}, a1[4] = {0,0,0,0};
                    #pragma unroll
                    for (int s = 0; s < 7; ++s) {
                        if (s < qhc) {
                            const int kk = qh + s;
                            #pragma unroll
                            for (int dk = 0; dk < 4; ++dk) {
                                const float* hr = sH12 + (kk * 4 + dk) * 12;  // h2(t-1)
                                DK_BODY(hr, wH0[s * 4 + dk], wH1[s * 4 + dk]);
                            }
                        }
                    }
                    float* gb = sG2 + (4 + g2) * 2448;
                    STORE_G(gb, jh, a0);
                    STORE_G(gb, jh + 102, a1);
                }
            }
        }
        if (t > 0 && tid >= 480 && tid < 488) {
            const int hb = tid - 480;
            float s = blin;
            #pragma unroll
            for (int jj = 0; jj < 51; ++jj)
                s = fmaf(sWlin[jj], sH12[(52 + jj) * 12 + hb], s);
            out[(b0 + hb) * TT + (t - 1)] = s;
        }
        __syncthreads();

        // ===== Phase C: gate2*W_ih2(t) (reads fresh h1(t)) =====
        if (t < TT && tid < 408) {
            u64 a0[4] = {0,0,0,0}, a1[4] = {0,0,0,0};
            const float* w0p = sW2i + r0 * 52;
            const float* w1p = sW2i + r1 * 52;
            #pragma unroll
            for (int s = 0; s < 4; ++s) {
                if (s < qc) {
                    const int kk = qb + s;
                    const float4 w0 = *(const float4*)(w0p + kk * 4);
                    const float4 w1 = *(const float4*)(w1p + kk * 4);
                    const float wz0[4] = {w0.x, w0.y, w0.z, w0.w};
                    const float wz1[4] = {w1.x, w1.y, w1.z, w1.w};
                    #pragma unroll
                    for (int dk = 0; dk < 4; ++dk) {
                        const float* hr = sH12 + (kk * 4 + dk) * 12;  // h1(t)
                        DK_BODY(hr, wz0[dk], wz1[dk]);
                    }
                }
            }
            float* gb = sG2 + g * 2448;
            STORE_G(gb, r0, a0);
            STORE_G(gb, r1, a1);
        }
        __syncthreads();
    }
}

extern "C" void kernel_launch(void* const* d_in, const int* in_sizes, int n_in,
                              void* d_out, int out_size) {
    const float* input = (const float*)d_in[0];
    const float* W_ih1 = (const float*)d_in[1];
    const float* W_hh1 = (const float*)d_in[2];
    const float* b_ih1 = (const float*)d_in[3];
    const float* b_hh1 = (const float*)d_in[4];
    const float* W_ih2 = (const float*)d_in[5];
    const float* W_hh2 = (const float*)d_in[6];
    const float* b_ih2 = (const float*)d_in[7];
    const float* b_hh2 = (const float*)d_in[8];
    const float* W_lin = (const float*)d_in[9];
    const float* b_lin = (const float*)d_in[10];
    float* out = (float*)d_out;

    cudaFuncSetAttribute(lstm_seq_kernel,
                         cudaFuncAttributeMaxDynamicSharedMemorySize, SMEM_BYTES);
    lstm_seq_kernel<<<NCTA, NTHR, SMEM_BYTES>>>(
        input, W_ih1, W_hh1, b_ih1, b_hh1,
        W_ih2, W_hh2, b_ih2, b_hh2, W_lin, b_lin, out);
}

// round 5
// speedup vs baseline: 1.1182x; 1.1182x over previous
#include <cuda_runtime.h>

#define Hh     51
#define H4     204
#define TT     1024
#define MB     8
#define NCTA   128
#define NTHR   448          // 14 warps

// ---- shared memory layout (float offsets) ----
// sW1  : [204][52]  W_hh1 rows, col 51 = 0 (stride 52 -> conflict-free LDS.128)
// sB1/sB2 : [204] combined biases; sWlin : [52]
// sX   : [1024][8]  input transposed (t-major)
// sH12 : [112][12]  rows 0..50 h1, 51 pad, 52..102 h2, 103..111 pad (cols 8..11 pad)
// sC   : [102][12]  c1 rows 0..50, c2 rows 51..101
// sG1  : [4][204][12] layer-1 partial gates   sG2 : [4][204][12] layer-2
#define OFF_W1    0
#define OFF_B1    10608
#define OFF_B2    10812
#define OFF_WLIN  11016
#define OFF_X     11072
#define OFF_H12   19264
#define OFF_C     20608
#define OFF_G1    21832
#define OFF_G2    31624
#define SMEM_FLOATS 41416
#define SMEM_BYTES  (SMEM_FLOATS * 4)

typedef unsigned long long u64;

__device__ __forceinline__ u64 splat2(float w) {
    unsigned int wi = __float_as_uint(w);
    u64 r;
    asm("mov.b64 %0, {%1, %1};" : "=l"(r) : "r"(wi));
    return r;
}
__device__ __forceinline__ void ffma2(u64& d, u64 a, u64 b) {
    asm("fma.rn.f32x2 %0, %1, %2, %0;" : "+l"(d) : "l"(a), "l"(b));
}
__device__ __forceinline__ float sigf(float x) {
    return __fdividef(1.0f, 1.0f + __expf(-x));
}
__device__ __forceinline__ float tanhfast(float x) {
    return 1.0f - __fdividef(2.0f, __expf(2.0f * x) + 1.0f);
}

// 8 FFMA2: accumulate w0,w1 x h[8 batch] into a0[4], a1[4]
#define DK_BODY(hr, w0s, w1s) { \
    const ulonglong2 hL = *(const ulonglong2*)(hr); \
    const ulonglong2 hH = *(const ulonglong2*)((hr) + 4); \
    const u64 p0 = splat2(w0s); \
    ffma2(a0[0], p0, hL.x); ffma2(a0[1], p0, hL.y); \
    ffma2(a0[2], p0, hH.x); ffma2(a0[3], p0, hH.y); \
    const u64 p1 = splat2(w1s); \
    ffma2(a1[0], p1, hL.x); ffma2(a1[1], p1, hL.y); \
    ffma2(a1[2], p1, hH.x); ffma2(a1[3], p1, hH.y); }

#define STORE_G(base, r, a) { ulonglong2 v; \
    v.x = (a)[0]; v.y = (a)[1]; *(ulonglong2*)((base) + (r) * 12)     = v; \
    v.x = (a)[2]; v.y = (a)[3]; *(ulonglong2*)((base) + (r) * 12 + 4) = v; }

// float2 sum of 4 partial-gate groups for gate row `row`, batch pair at col bo2
__device__ __forceinline__ float2 gs2(const float* g, int row, int bo2) {
    const float* p = g + row * 12 + bo2;
    float2 a = *(const float2*)p;
    const float2 b = *(const float2*)(p + 2448);
    const float2 c = *(const float2*)(p + 4896);
    const float2 d = *(const float2*)(p + 7344);
    a.x += b.x + c.x + d.x;
    a.y += b.y + c.y + d.y;
    return a;
}

// state update for one hidden j, one batch pair (2 elements)
__device__ __forceinline__ void upd2(const float* sG, const float* sB,
                                     float* cp, float* hp, int j, int bo2) {
    const float2 gi = gs2(sG, j, bo2);
    const float2 gf = gs2(sG, 51 + j, bo2);
    const float2 gg = gs2(sG, 102 + j, bo2);
    const float2 go = gs2(sG, 153 + j, bo2);
    const float bi = sB[j], bf = sB[51 + j], bg = sB[102 + j], bq = sB[153 + j];
    float2 c = *(float2*)cp, h;
    {
        const float iv = sigf(gi.x + bi), fv = sigf(gf.x + bf);
        const float gv = tanhfast(gg.x + bg), ov = sigf(go.x + bq);
        const float cn = fv * c.x + iv * gv;
        c.x = cn; h.x = ov * tanhfast(cn);
    }
    {
        const float iv = sigf(gi.y + bi), fv = sigf(gf.y + bf);
        const float gv = tanhfast(gg.y + bg), ov = sigf(go.y + bq);
        const float cn = fv * c.y + iv * gv;
        c.y = cn; h.y = ov * tanhfast(cn);
    }
    *(float2*)cp = c;
    *(float2*)hp = h;
}

__global__ __launch_bounds__(NTHR, 1)
void lstm_seq_kernel(const float* __restrict__ input,
                     const float* __restrict__ W_ih1, const float* __restrict__ W_hh1,
                     const float* __restrict__ b_ih1, const float* __restrict__ b_hh1,
                     const float* __restrict__ W_ih2, const float* __restrict__ W_hh2,
                     const float* __restrict__ b_ih2, const float* __restrict__ b_hh2,
                     const float* __restrict__ W_lin, const float* __restrict__ b_lin,
                     float* __restrict__ out)
{
    extern __shared__ float sm[];
    float* sW1   = sm + OFF_W1;
    float* sB1   = sm + OFF_B1;
    float* sB2   = sm + OFF_B2;
    float* sWlin = sm + OFF_WLIN;
    float* sX    = sm + OFF_X;
    float* sH12  = sm + OFF_H12;
    float* sC    = sm + OFF_C;
    float* sG1   = sm + OFF_G1;
    float* sG2   = sm + OFF_G2;

    const int tid = threadIdx.x;
    const int b0  = blockIdx.x * MB;

    // ---------------- one-time staging ----------------
    for (int i = tid; i < H4 * Hh; i += NTHR) {
        const int r = i / Hh, k = i % Hh;
        sW1[r * 52 + k] = W_hh1[i];
    }
    for (int r = tid; r < H4; r += NTHR) {
        sW1[r * 52 + 51] = 0.0f;
        sB1[r] = b_ih1[r] + b_hh1[r];
        sB2[r] = b_ih2[r] + b_hh2[r];
    }
    if (tid < Hh) sWlin[tid] = W_lin[tid];
    for (int i = tid; i < MB * TT; i += NTHR) {
        const int b = i >> 10, t = i & 1023;
        sX[t * MB + b] = input[b0 * TT + i];
    }
    for (int i = tid; i < 112 * 12; i += NTHR) sH12[i] = 0.0f;
    for (int i = tid; i < 102 * 12; i += NTHR) sC[i]  = 0.0f;

    // ---------------- gate-thread role + register weights ----------------
    const int g  = tid / 112;           // k-group 0..3 (warps 3,10 mixed; rest uniform)
    const int jj = tid - g * 112;       // 0..111; gate-active if < 102
    const bool gate_act = (jj < 102);
    const int r0 = jj, r1 = jj + 102;
    const int qb1 = (g == 0) ? 0 : (3 * g + 1);     // L1 quads {0-3,4-6,7-9,10-12}
    const int qc1 = (g == 0) ? 4 : 3;
    const int qb2 = (g < 2) ? (7 * g) : (6 * g + 2); // L2 quads {0-6,7-13,14-19,20-25}
    const int qc2 = (g < 2) ? 7 : 6;

    float wih0 = 0.0f, wih1v = 0.0f;
    float wB0[28], wB1[28];             // layer-2 weights, register-resident
    #pragma unroll
    for (int i = 0; i < 28; ++i) { wB0[i] = 0.0f; wB1[i] = 0.0f; }

    if (gate_act) {
        if (g == 0) { wih0 = W_ih1[r0]; wih1v = W_ih1[r1]; }
        #pragma unroll
        for (int s = 0; s < 7; ++s) {
            if (s < qc2) {
                #pragma unroll
                for (int dk = 0; dk < 4; ++dk) {
                    const int col = (qb2 + s) * 4 + dk;   // 0..103
                    float v0 = 0.0f, v1 = 0.0f;
                    if (col < 51) {
                        v0 = W_ih2[r0 * 51 + col];
                        v1 = W_ih2[r1 * 51 + col];
                    } else if (col >= 52 && col < 103) {
                        v0 = W_hh2[r0 * 51 + col - 52];
                        v1 = W_hh2[r1 * 51 + col - 52];
                    }
                    wB0[s * 4 + dk] = v0;
                    wB1[s * 4 + dk] = v1;
                }
            }
        }
    }
    const float* w1p0 = sW1 + r0 * 52;
    const float* w1p1 = sW1 + r1 * 52;
    float* gb1 = sG1 + g * 2448;
    float* gb2 = sG2 + g * 2448;

    // update-thread role (tids 0..203): hidden j, batch pair
    const int ju  = tid >> 2;           // 0..50 valid
    const int bo2 = (tid & 3) * 2;      // 0,2,4,6
    const bool upd_act = (tid < 204) && (ju < 51);

    const float blin = b_lin[0];
    __syncthreads();

    // ---------------- time loop: 4 phases ----------------
    for (int t = 0; t < TT; ++t) {
        // ===== Phase A: gate1(t) || head(t-1) =====
        if (gate_act) {
            u64 a0[4] = {0,0,0,0}, a1[4] = {0,0,0,0};
            if (g == 0) {
                const float* xp = sX + t * MB;
                const ulonglong2 xL = *(const ulonglong2*)xp;
                const ulonglong2 xH = *(const ulonglong2*)(xp + 4);
                const u64 p0 = splat2(wih0), p1 = splat2(wih1v);
                ffma2(a0[0], p0, xL.x); ffma2(a0[1], p0, xL.y);
                ffma2(a0[2], p0, xH.x); ffma2(a0[3], p0, xH.y);
                ffma2(a1[0], p1, xL.x); ffma2(a1[1], p1, xL.y);
                ffma2(a1[2], p1, xH.x); ffma2(a1[3], p1, xH.y);
            }
            #pragma unroll
            for (int s = 0; s < 4; ++s) {
                if (s < qc1) {
                    const int kk = qb1 + s;
                    const float4 w0 = *(const float4*)(w1p0 + kk * 4);
                    const float4 w1 = *(const float4*)(w1p1 + kk * 4);
                    const float wz0[4] = {w0.x, w0.y, w0.z, w0.w};
                    const float wz1[4] = {w1.x, w1.y, w1.z, w1.w};
                    #pragma unroll
                    for (int dk = 0; dk < 4; ++dk) {
                        const float* hr = sH12 + (kk * 4 + dk) * 12;   // h1(t-1), rows 0..51
                        DK_BODY(hr, wz0[dk], wz1[dk]);
                    }
                }
            }
            STORE_G(gb1, r0, a0);
            STORE_G(gb1, r1, a1);
        } else if (tid >= 438 && tid < 446 && t > 0) {
            // head(t-1): reads h2(t-1) written in phase D of previous step
            const int hb = tid - 438;
            float s = blin;
            #pragma unroll
            for (int k = 0; k < Hh; ++k)
                s = fmaf(sWlin[k], sH12[(52 + k) * 12 + hb], s);
            out[(b0 + hb) * TT + (t - 1)] = s;
        }
        __syncthreads();

        // ===== Phase B: update1(t) =====
        if (upd_act)
            upd2(sG1, sB1, sC + ju * 12 + bo2, sH12 + ju * 12 + bo2, ju, bo2);
        __syncthreads();

        // ===== Phase C: gate2(t) (reads h1(t) rows 0..51 + h2(t-1) rows 52..103) =====
        if (gate_act) {
            u64 a0[4] = {0,0,0,0}, a1[4] = {0,0,0,0};
            #pragma unroll
            for (int s = 0; s < 7; ++s) {
                if (s < qc2) {
                    const int kk = qb2 + s;
                    #pragma unroll
                    for (int dk = 0; dk < 4; ++dk) {
                        const float* hr = sH12 + (kk * 4 + dk) * 12;   // rows 0..103
                        DK_BODY(hr, wB0[s * 4 + dk], wB1[s * 4 + dk]);
                    }
                }
            }
            STORE_G(gb2, r0, a0);
            STORE_G(gb2, r1, a1);
        }
        __syncthreads();

        // ===== Phase D: update2(t) =====
        if (upd_act)
            upd2(sG2, sB2, sC + (51 + ju) * 12 + bo2,
                 sH12 + (52 + ju) * 12 + bo2, ju, bo2);
        __syncthreads();
    }

    // epilogue head for t = TT-1
    if (tid >= 438 && tid < 446) {
        const int hb = tid - 438;
        float s = blin;
        #pragma unroll
        for (int k = 0; k < Hh; ++k)
            s = fmaf(sWlin[k], sH12[(52 + k) * 12 + hb], s);
        out[(b0 + hb) * TT + (TT - 1)] = s;
    }
}

extern "C" void kernel_launch(void* const* d_in, const int* in_sizes, int n_in,
                              void* d_out, int out_size) {
    const float* input = (const float*)d_in[0];
    const float* W_ih1 = (const float*)d_in[1];
    const float* W_hh1 = (const float*)d_in[2];
    const float* b_ih1 = (const float*)d_in[3];
    const float* b_hh1 = (const float*)d_in[4];
    const float* W_ih2 = (const float*)d_in[5];
    const float* W_hh2 = (const float*)d_in[6];
    const float* b_ih2 = (const float*)d_in[7];
    const float* b_hh2 = (const float*)d_in[8];
    const float* W_lin = (const float*)d_in[9];
    const float* b_lin = (const float*)d_in[10];
    float* out = (float*)d_out;

    cudaFuncSetAttribute(lstm_seq_kernel,
                         cudaFuncAttributeMaxDynamicSharedMemorySize, SMEM_BYTES);
    lstm_seq_kernel<<<NCTA, NTHR, SMEM_BYTES>>>(
        input, W_ih1, W_hh1, b_ih1, b_hh1,
        W_ih2, W_hh2, b_ih2, b_hh2, W_lin, b_lin, out);
}